// round 10
// baseline (speedup 1.0000x reference)
#include <cuda_runtime.h>
#include <cuda_fp16.h>
#include <cstdint>
#include <cstddef>

// Problem constants
#define Bb 4
#define Tt 1024
#define Cc 1024
#define Hh 16
#define Dd 64
#define Mm 4096      // B*T tokens
#define FF 4096      // ffn hidden

// ---------------- scratch (device globals; no allocation) ----------------
__device__ __half g_hh[Mm * Cc];        // LN output (fp16)
__device__ __half g_qh[Mm * Cc];
__device__ __half g_kh[Mm * Cc];
__device__ __half g_vh[Mm * Cc];
__device__ __half g_ah[Mm * Cc];        // attention output
__device__ __half g_ffh[Mm * FF];       // FFN hidden (fp16)
__device__ __half g_wch[8 * Cc * Cc];   // 8 CxC weights fp16
__device__ __half g_w1h[Cc * FF];
__device__ __half g_w2h[FF * Cc];
__device__ __half g_ench[Mm * Cc];      // encoder_out fp16

// ---------------- helpers ----------------
__device__ __forceinline__ void cp16(void* dst_smem, const void* src) {
    uint32_t sa = (uint32_t)__cvta_generic_to_shared(dst_smem);
    asm volatile("cp.async.cg.shared.global [%0], [%1], 16;\n" :: "r"(sa), "l"(src));
}
__device__ __forceinline__ void ldsm4(uint32_t r[4], uint32_t a) {
    asm volatile("ldmatrix.sync.aligned.m8n8.x4.shared.b16 {%0,%1,%2,%3}, [%4];"
                 : "=r"(r[0]), "=r"(r[1]), "=r"(r[2]), "=r"(r[3]) : "r"(a));
}
__device__ __forceinline__ void ldsm4t(uint32_t r[4], uint32_t a) {
    asm volatile("ldmatrix.sync.aligned.m8n8.x4.trans.shared.b16 {%0,%1,%2,%3}, [%4];"
                 : "=r"(r[0]), "=r"(r[1]), "=r"(r[2]), "=r"(r[3]) : "r"(a));
}
__device__ __forceinline__ void mma16(float c[4], const uint32_t a[4], const uint32_t b[2]) {
    asm volatile(
        "mma.sync.aligned.m16n8k16.row.col.f32.f16.f16.f32 "
        "{%0,%1,%2,%3}, {%4,%5,%6,%7}, {%8,%9}, {%0,%1,%2,%3};\n"
        : "+f"(c[0]), "+f"(c[1]), "+f"(c[2]), "+f"(c[3])
        : "r"(a[0]), "r"(a[1]), "r"(a[2]), "r"(a[3]), "r"(b[0]), "r"(b[1]));
}
__device__ __forceinline__ uint32_t h2pack(float lo, float hi) {
    __half2 h = __floats2half2_rn(lo, hi);
    return *reinterpret_cast<uint32_t*>(&h);
}

// ---------------- fused fp32 -> fp16 convert (all tensors, one launch) ----------------
// Segments: 8 x CC (2^18 float4 each), then 3 x (2^20 float4): ff_w1, ff_w2, enc.
#define S1_LOG 18
#define S2_LOG 20
#define N_S1 8
#define CVT_TOTAL ((N_S1 << S1_LOG) + (3 << S2_LOG))   // 5,242,880 float4

struct CvtArgs {
    const float* src[11];
    __half* dst[11];
};

__global__ __launch_bounds__(256)
void f2h_all(CvtArgs args) {
    const int nt = gridDim.x * blockDim.x;
    int i = blockIdx.x * blockDim.x + threadIdx.x;
#pragma unroll
    for (int rep = 0; rep < 4; rep++) {
        if (i < CVT_TOTAL) {
            int seg, off;
            if (i < (N_S1 << S1_LOG)) {
                seg = i >> S1_LOG;
                off = i & ((1 << S1_LOG) - 1);
            } else {
                const int j = i - (N_S1 << S1_LOG);
                seg = N_S1 + (j >> S2_LOG);
                off = j & ((1 << S2_LOG) - 1);
            }
            const float4 v = ((const float4*)args.src[seg])[off];
            ((uint2*)args.dst[seg])[off] = make_uint2(h2pack(v.x, v.y), h2pack(v.z, v.w));
        }
        i += nt;
    }
}

// ---------------- block reduction ----------------
__device__ __forceinline__ float block_sum_256(float v) {
    __shared__ float sh[8];
    const int lane = threadIdx.x & 31;
    const int w = threadIdx.x >> 5;
#pragma unroll
    for (int o = 16; o > 0; o >>= 1) v += __shfl_xor_sync(0xffffffffu, v, o);
    if (lane == 0) sh[w] = v;
    __syncthreads();
    float r = (lane < 8) ? sh[lane] : 0.f;
#pragma unroll
    for (int o = 4; o > 0; o >>= 1) r += __shfl_xor_sync(0xffffffffu, r, o);
    float total = __shfl_sync(0xffffffffu, r, 0);
    __syncthreads();
    return total;
}

// ---------------- layernorm (fp32 in, fp16 out) ----------------
__global__ __launch_bounds__(256)
void ln_kernel(const float* __restrict__ x, const float* __restrict__ g,
               const float* __restrict__ b, __half* __restrict__ out) {
    const size_t row = blockIdx.x;
    const int t = threadIdx.x;
    const float4 v = ((const float4*)(x + row * Cc))[t];
    float s = v.x + v.y + v.z + v.w;
    const float mean = block_sum_256(s) * (1.f / Cc);
    const float dx = v.x - mean, dy = v.y - mean, dz = v.z - mean, dw = v.w - mean;
    const float var = block_sum_256(dx*dx + dy*dy + dz*dz + dw*dw) * (1.f / Cc);
    const float inv = rsqrtf(var + 1e-5f);
    const float4 gg = ((const float4*)g)[t];
    const float4 bb = ((const float4*)b)[t];
    ((uint2*)(out + row * Cc))[t] = make_uint2(
        h2pack(dx * inv * gg.x + bb.x, dy * inv * gg.y + bb.y),
        h2pack(dz * inv * gg.z + bb.z, dw * inv * gg.w + bb.w));
}

// ---------------- fp16 tensor-core GEMM ----------------
// CTA 128x128, 8 warps (2m x 4n), warp 64x32, k-tile 32, 3-stage cp.async.
#define GA_P 40                        // A smem pitch (halfs)
#define GB_P 136                       // B smem pitch (halfs)
#define GA_SZ (128 * GA_P)
#define GB_SZ (32 * GB_P)
#define GSTG (GA_SZ + GB_SZ)
#define GEMM_SMEM (3 * GSTG * 2)       // bytes (56832)

template<bool RELU, bool RES, bool OUTH>
__global__ __launch_bounds__(256, 2)
void gemm_h(const __half* __restrict__ A, const __half* __restrict__ W,
            const float* __restrict__ bias, const float* __restrict__ res,
            void* __restrict__ outp, int M, int N, int K) {
    extern __shared__ __half smh[];
    const uint32_t sbase = (uint32_t)__cvta_generic_to_shared(smh);

    const int m0 = blockIdx.y * 128;
    const int n0 = blockIdx.x * 128;
    const int t = threadIdx.x;
    const int lane = t & 31;
    const int wid = t >> 5;
    const int g = lane >> 2;
    const int tig = lane & 3;
    const int wm = (wid & 1) * 64;
    const int wn = (wid >> 1) * 32;

    float acc[4][4][4];
#pragma unroll
    for (int mi = 0; mi < 4; mi++)
#pragma unroll
        for (int ni = 0; ni < 4; ni++)
#pragma unroll
            for (int r = 0; r < 4; r++) acc[mi][ni][r] = 0.f;

    const int ntk = K >> 5;

    auto load_tile = [&](int kt, int s) {
        __half* As = smh + s * GSTG;
        __half* Bs = As + GA_SZ;
        const int k0 = kt * 32;
#pragma unroll
        for (int i = 0; i < 2; i++) {
            const int idx = t + i * 256;
            const int r = idx >> 2, sg = idx & 3;
            cp16(As + r * GA_P + sg * 8, A + (size_t)(m0 + r) * K + k0 + sg * 8);
        }
#pragma unroll
        for (int i = 0; i < 2; i++) {
            const int idx = t + i * 256;
            const int r = idx >> 4, sg = idx & 15;
            cp16(Bs + r * GB_P + sg * 8, W + (size_t)(k0 + r) * N + n0 + sg * 8);
        }
        asm volatile("cp.async.commit_group;\n");
    };

    load_tile(0, 0);
    load_tile(1, 1);

    for (int kt = 0; kt < ntk; kt++) {
        const int buf = kt % 3;
        if (kt + 1 < ntk) asm volatile("cp.async.wait_group 1;\n");
        else              asm volatile("cp.async.wait_group 0;\n");
        __syncthreads();   // tile kt ready; all warps done reading buf (kt+2)%3

        if (kt + 2 < ntk) load_tile(kt + 2, (kt + 2) % 3);

        const uint32_t ab = sbase + buf * GSTG * 2;          // A bytes
        const uint32_t bb = ab + GA_SZ * 2;                  // B bytes
#pragma unroll
        for (int ks = 0; ks < 2; ks++) {
            uint32_t af[4][4];
#pragma unroll
            for (int mi = 0; mi < 4; mi++)
                ldsm4(af[mi], ab + ((wm + mi * 16 + (lane & 15)) * GA_P
                                    + ks * 16 + (lane >> 4) * 8) * 2);
            uint32_t bf[2][4];
#pragma unroll
            for (int p = 0; p < 2; p++)
                ldsm4t(bf[p], bb + ((ks * 16 + (lane & 7) + ((lane >> 3) & 1) * 8) * GB_P
                                    + wn + p * 16 + (lane >> 4) * 8) * 2);
#pragma unroll
            for (int mi = 0; mi < 4; mi++)
#pragma unroll
                for (int ni = 0; ni < 4; ni++)
                    mma16(acc[mi][ni], af[mi], &bf[ni >> 1][(ni & 1) * 2]);
        }
    }

    // epilogue
#pragma unroll
    for (int mi = 0; mi < 4; mi++) {
        const int m = m0 + wm + mi * 16 + g;
#pragma unroll
        for (int ni = 0; ni < 4; ni++) {
            const int n = n0 + wn + ni * 8 + tig * 2;
            float v0x = acc[mi][ni][0], v0y = acc[mi][ni][1];
            float v1x = acc[mi][ni][2], v1y = acc[mi][ni][3];
            if (bias) {
                const float b0 = bias[n], b1 = bias[n + 1];
                v0x += b0; v0y += b1; v1x += b0; v1y += b1;
            }
            if (RES) {
                const float2 r0 = *(const float2*)(res + (size_t)m * N + n);
                const float2 r1 = *(const float2*)(res + (size_t)(m + 8) * N + n);
                v0x += r0.x; v0y += r0.y; v1x += r1.x; v1y += r1.y;
            }
            if (RELU) {
                v0x = fmaxf(v0x, 0.f); v0y = fmaxf(v0y, 0.f);
                v1x = fmaxf(v1x, 0.f); v1y = fmaxf(v1y, 0.f);
            }
            if (OUTH) {
                __half* o = (__half*)outp;
                *(uint32_t*)(o + (size_t)m * N + n) = h2pack(v0x, v0y);
                *(uint32_t*)(o + (size_t)(m + 8) * N + n) = h2pack(v1x, v1y);
            } else {
                float* o = (float*)outp;
                *(float2*)(o + (size_t)m * N + n) = make_float2(v0x, v0y);
                *(float2*)(o + (size_t)(m + 8) * N + n) = make_float2(v1x, v1y);
            }
        }
    }
}

// ---------------- fp16 tensor-core flash attention ----------------
#define AP 72
#define AQ_SZ (64 * AP)                // halfs
#define ATTN_SMEM ((AQ_SZ * 5) * 2)    // Q + 2K + 2V, bytes (46080)

template<bool CAUSAL>
__global__ __launch_bounds__(128)
void attn_h(const __half* __restrict__ Qg, const __half* __restrict__ Kg,
            const __half* __restrict__ Vg, __half* __restrict__ Og) {
    extern __shared__ __half smh[];
    __half* Qs = smh;
    __half* Ks = smh + AQ_SZ;
    __half* Vs = Ks + 2 * AQ_SZ;
    const uint32_t sbase = (uint32_t)__cvta_generic_to_shared(smh);
    const uint32_t qb = sbase;
    const uint32_t kb = sbase + AQ_SZ * 2;
    const uint32_t vb = kb + 2 * AQ_SZ * 2;

    const int qt = blockIdx.x;
    const int bh = blockIdx.y;
    const int b = bh >> 4;
    const int h = bh & 15;
    const int q0 = qt * 64;
    const int t = threadIdx.x;
    const int lane = t & 31;
    const int w = t >> 5;
    const int g = lane >> 2;
    const int tig = lane & 3;
    const int wm = w * 16;

    const __half* Qbase = Qg + ((size_t)(b * Tt + q0)) * Cc + h * Dd;
    const __half* Kbase = Kg + ((size_t)(b * Tt)) * Cc + h * Dd;
    const __half* Vbase = Vg + ((size_t)(b * Tt)) * Cc + h * Dd;

#pragma unroll
    for (int i = 0; i < 4; i++) {
        const int idx = t + i * 128;
        const int r = idx >> 3, sg = idx & 7;
        cp16(Qs + r * AP + sg * 8, Qbase + (size_t)r * Cc + sg * 8);
        cp16(Ks + r * AP + sg * 8, Kbase + (size_t)r * Cc + sg * 8);
        cp16(Vs + r * AP + sg * 8, Vbase + (size_t)r * Cc + sg * 8);
    }
    asm volatile("cp.async.commit_group;\n");

    float m0r = -1e30f, m1r = -1e30f, l0 = 0.f, l1 = 0.f;
    float oacc[8][4];
#pragma unroll
    for (int nf = 0; nf < 8; nf++)
#pragma unroll
        for (int r = 0; r < 4; r++) oacc[nf][r] = 0.f;

    const int ktend = CAUSAL ? qt : (Tt / 64 - 1);
    for (int kt = 0; kt <= ktend; kt++) {
        const int buf = kt & 1;
        if (kt < ktend) {
            const __half* Kp = Kbase + (size_t)(kt + 1) * 64 * Cc;
            const __half* Vp = Vbase + (size_t)(kt + 1) * 64 * Cc;
            __half* Kd = Ks + (buf ^ 1) * AQ_SZ;
            __half* Vd = Vs + (buf ^ 1) * AQ_SZ;
#pragma unroll
            for (int i = 0; i < 4; i++) {
                const int idx = t + i * 128;
                const int r = idx >> 3, sg = idx & 7;
                cp16(Kd + r * AP + sg * 8, Kp + (size_t)r * Cc + sg * 8);
                cp16(Vd + r * AP + sg * 8, Vp + (size_t)r * Cc + sg * 8);
            }
            asm volatile("cp.async.commit_group;\n");
            asm volatile("cp.async.wait_group 1;\n");
        } else {
            asm volatile("cp.async.wait_group 0;\n");
        }
        __syncthreads();

        const uint32_t kbb = kb + buf * AQ_SZ * 2;
        const uint32_t vbb = vb + buf * AQ_SZ * 2;

        float sc[8][4];
#pragma unroll
        for (int nf = 0; nf < 8; nf++)
#pragma unroll
            for (int r = 0; r < 4; r++) sc[nf][r] = 0.f;
#pragma unroll
        for (int ks = 0; ks < 4; ks++) {
            uint32_t a[4];
            ldsm4(a, qb + ((wm + (lane & 15)) * AP + ks * 16 + (lane >> 4) * 8) * 2);
#pragma unroll
            for (int p = 0; p < 4; p++) {
                uint32_t bf[4];
                ldsm4(bf, kbb + ((p * 16 + (lane >> 4) * 8 + (lane & 7)) * AP
                                 + ks * 16 + ((lane >> 3) & 1) * 8) * 2);
                mma16(sc[2 * p], a, &bf[0]);
                mma16(sc[2 * p + 1], a, &bf[2]);
            }
        }

        const int r0g = q0 + wm + g;
        const int r1g = r0g + 8;
#pragma unroll
        for (int nf = 0; nf < 8; nf++) {
            sc[nf][0] *= 0.125f; sc[nf][1] *= 0.125f;
            sc[nf][2] *= 0.125f; sc[nf][3] *= 0.125f;
            if (CAUSAL && kt == qt) {
                const int c0 = kt * 64 + nf * 8 + tig * 2;
                if (c0 > r0g) sc[nf][0] = -1e30f;
                if (c0 + 1 > r0g) sc[nf][1] = -1e30f;
                if (c0 > r1g) sc[nf][2] = -1e30f;
                if (c0 + 1 > r1g) sc[nf][3] = -1e30f;
            }
        }

        float mx0 = -1e30f, mx1 = -1e30f;
#pragma unroll
        for (int nf = 0; nf < 8; nf++) {
            mx0 = fmaxf(mx0, fmaxf(sc[nf][0], sc[nf][1]));
            mx1 = fmaxf(mx1, fmaxf(sc[nf][2], sc[nf][3]));
        }
        mx0 = fmaxf(mx0, __shfl_xor_sync(0xffffffffu, mx0, 1));
        mx0 = fmaxf(mx0, __shfl_xor_sync(0xffffffffu, mx0, 2));
        mx1 = fmaxf(mx1, __shfl_xor_sync(0xffffffffu, mx1, 1));
        mx1 = fmaxf(mx1, __shfl_xor_sync(0xffffffffu, mx1, 2));
        const float nm0 = fmaxf(m0r, mx0);
        const float nm1 = fmaxf(m1r, mx1);
        const float al0 = __expf(m0r - nm0);
        const float al1 = __expf(m1r - nm1);
        float rs0 = 0.f, rs1 = 0.f;
#pragma unroll
        for (int nf = 0; nf < 8; nf++) {
            sc[nf][0] = __expf(sc[nf][0] - nm0);
            sc[nf][1] = __expf(sc[nf][1] - nm0);
            sc[nf][2] = __expf(sc[nf][2] - nm1);
            sc[nf][3] = __expf(sc[nf][3] - nm1);
            rs0 += sc[nf][0] + sc[nf][1];
            rs1 += sc[nf][2] + sc[nf][3];
        }
        rs0 += __shfl_xor_sync(0xffffffffu, rs0, 1);
        rs0 += __shfl_xor_sync(0xffffffffu, rs0, 2);
        rs1 += __shfl_xor_sync(0xffffffffu, rs1, 1);
        rs1 += __shfl_xor_sync(0xffffffffu, rs1, 2);
        l0 = l0 * al0 + rs0;
        l1 = l1 * al1 + rs1;
        m0r = nm0; m1r = nm1;
#pragma unroll
        for (int nf = 0; nf < 8; nf++) {
            oacc[nf][0] *= al0; oacc[nf][1] *= al0;
            oacc[nf][2] *= al1; oacc[nf][3] *= al1;
        }

#pragma unroll
        for (int ks = 0; ks < 4; ks++) {
            uint32_t a[4];
            a[0] = h2pack(sc[2 * ks][0], sc[2 * ks][1]);
            a[1] = h2pack(sc[2 * ks][2], sc[2 * ks][3]);
            a[2] = h2pack(sc[2 * ks + 1][0], sc[2 * ks + 1][1]);
            a[3] = h2pack(sc[2 * ks + 1][2], sc[2 * ks + 1][3]);
#pragma unroll
            for (int p = 0; p < 4; p++) {
                uint32_t bf[4];
                ldsm4t(bf, vbb + ((ks * 16 + (lane & 7) + ((lane >> 3) & 1) * 8) * AP
                                  + p * 16 + (lane >> 4) * 8) * 2);
                mma16(oacc[2 * p], a, &bf[0]);
                mma16(oacc[2 * p + 1], a, &bf[2]);
            }
        }
        __syncthreads();
    }

    const float inv0 = 1.f / l0;
    const float inv1 = 1.f / l1;
    __half* orow0 = Og + ((size_t)(b * Tt + q0 + wm + g)) * Cc + h * Dd;
    __half* orow1 = orow0 + (size_t)8 * Cc;
#pragma unroll
    for (int nf = 0; nf < 8; nf++) {
        *(uint32_t*)(orow0 + nf * 8 + tig * 2) = h2pack(oacc[nf][0] * inv0, oacc[nf][1] * inv0);
        *(uint32_t*)(orow1 + nf * 8 + tig * 2) = h2pack(oacc[nf][2] * inv1, oacc[nf][3] * inv1);
    }
}

// ---------------- driver ----------------
extern "C" void kernel_launch(void* const* d_in, const int* in_sizes, int n_in,
                              void* d_out, int out_size) {
    const float* x      = (const float*)d_in[0];
    const float* enc    = (const float*)d_in[1];
    const float* sa_wq  = (const float*)d_in[2];
    const float* sa_wk  = (const float*)d_in[3];
    const float* sa_wv  = (const float*)d_in[4];
    const float* sa_wo  = (const float*)d_in[5];
    const float* sa_bo  = (const float*)d_in[6];
    const float* ca_wq  = (const float*)d_in[7];
    const float* ca_wk  = (const float*)d_in[8];
    const float* ca_wv  = (const float*)d_in[9];
    const float* ca_wo  = (const float*)d_in[10];
    const float* ca_bo  = (const float*)d_in[11];
    const float* ff_w1  = (const float*)d_in[12];
    const float* ff_b1  = (const float*)d_in[13];
    const float* ff_w2  = (const float*)d_in[14];
    const float* ff_b2  = (const float*)d_in[15];
    const float* ln1_g  = (const float*)d_in[16];
    const float* ln1_b  = (const float*)d_in[17];
    const float* ln2_g  = (const float*)d_in[18];
    const float* ln2_b  = (const float*)d_in[19];
    const float* ln3_g  = (const float*)d_in[20];
    const float* ln3_b  = (const float*)d_in[21];
    float* out = (float*)d_out;

    __half *hh, *qh, *kh, *vh, *ah, *ffh, *wch, *w1h, *w2h, *ench;
    cudaGetSymbolAddress((void**)&hh,   g_hh);
    cudaGetSymbolAddress((void**)&qh,   g_qh);
    cudaGetSymbolAddress((void**)&kh,   g_kh);
    cudaGetSymbolAddress((void**)&vh,   g_vh);
    cudaGetSymbolAddress((void**)&ah,   g_ah);
    cudaGetSymbolAddress((void**)&ffh,  g_ffh);
    cudaGetSymbolAddress((void**)&wch,  g_wch);
    cudaGetSymbolAddress((void**)&w1h,  g_w1h);
    cudaGetSymbolAddress((void**)&w2h,  g_w2h);
    cudaGetSymbolAddress((void**)&ench, g_ench);

    cudaFuncSetAttribute((const void*)attn_h<true>,
                         cudaFuncAttributeMaxDynamicSharedMemorySize, ATTN_SMEM);
    cudaFuncSetAttribute((const void*)attn_h<false>,
                         cudaFuncAttributeMaxDynamicSharedMemorySize, ATTN_SMEM);
    cudaFuncSetAttribute((const void*)gemm_h<false, false, true>,
                         cudaFuncAttributeMaxDynamicSharedMemorySize, GEMM_SMEM);
    cudaFuncSetAttribute((const void*)gemm_h<false, true, false>,
                         cudaFuncAttributeMaxDynamicSharedMemorySize, GEMM_SMEM);
    cudaFuncSetAttribute((const void*)gemm_h<true, false, true>,
                         cudaFuncAttributeMaxDynamicSharedMemorySize, GEMM_SMEM);

    const int CC = Cc * Cc;

    // fused conversion: 8 CxC weights, ff_w1, ff_w2, enc — ONE launch
    __half* wp[8] = {wch + 0*CC, wch + 1*CC, wch + 2*CC, wch + 3*CC,
                     wch + 4*CC, wch + 5*CC, wch + 6*CC, wch + 7*CC};
    CvtArgs ca;
    const float* ws[8] = {sa_wq, sa_wk, sa_wv, sa_wo, ca_wq, ca_wk, ca_wv, ca_wo};
    for (int i = 0; i < 8; i++) { ca.src[i] = ws[i]; ca.dst[i] = wp[i]; }
    ca.src[8] = ff_w1; ca.dst[8] = w1h;
    ca.src[9] = ff_w2; ca.dst[9] = w2h;
    ca.src[10] = enc;  ca.dst[10] = ench;
    f2h_all<<<(CVT_TOTAL / 4 + 255) / 256, 256>>>(ca);

    const dim3 gP(Cc / 128, Mm / 128);     // 8 x 32
    const dim3 gF1(FF / 128, Mm / 128);    // 32 x 32
    const dim3 gA(Tt / 64, Bb * Hh);

    // ---- self-attention block ----
    ln_kernel<<<Mm, 256>>>(x, ln1_g, ln1_b, hh);
    gemm_h<false, false, true><<<gP, 256, GEMM_SMEM>>>(hh, wp[0], nullptr, nullptr, qh, Mm, Cc, Cc);
    gemm_h<false, false, true><<<gP, 256, GEMM_SMEM>>>(hh, wp[1], nullptr, nullptr, kh, Mm, Cc, Cc);
    gemm_h<false, false, true><<<gP, 256, GEMM_SMEM>>>(hh, wp[2], nullptr, nullptr, vh, Mm, Cc, Cc);
    attn_h<true><<<gA, 128, ATTN_SMEM>>>(qh, kh, vh, ah);
    gemm_h<false, true, false><<<gP, 256, GEMM_SMEM>>>(ah, wp[3], sa_bo, x, out, Mm, Cc, Cc);

    // ---- cross-attention block ----
    ln_kernel<<<Mm, 256>>>(out, ln2_g, ln2_b, hh);
    gemm_h<false, false, true><<<gP, 256, GEMM_SMEM>>>(hh,   wp[4], nullptr, nullptr, qh, Mm, Cc, Cc);
    gemm_h<false, false, true><<<gP, 256, GEMM_SMEM>>>(ench, wp[5], nullptr, nullptr, kh, Mm, Cc, Cc);
    gemm_h<false, false, true><<<gP, 256, GEMM_SMEM>>>(ench, wp[6], nullptr, nullptr, vh, Mm, Cc, Cc);
    attn_h<false><<<gA, 128, ATTN_SMEM>>>(qh, kh, vh, ah);
    gemm_h<false, true, false><<<gP, 256, GEMM_SMEM>>>(ah, wp[7], ca_bo, out, out, Mm, Cc, Cc);

    // ---- FFN block ----
    ln_kernel<<<Mm, 256>>>(out, ln3_g, ln3_b, hh);
    gemm_h<true,  false, true><<<gF1, 256, GEMM_SMEM>>>(hh,  w1h, ff_b1, nullptr, ffh, Mm, FF, Cc);
    gemm_h<false, true, false><<<gP,  256, GEMM_SMEM>>>(ffh, w2h, ff_b2, out, out, Mm, Cc, FF);
}

// round 13
// speedup vs baseline: 1.0375x; 1.0375x over previous
#include <cuda_runtime.h>
#include <cuda_fp16.h>
#include <cstdint>
#include <cstddef>

// Problem constants
#define Bb 4
#define Tt 1024
#define Cc 1024
#define Hh 16
#define Dd 64
#define Mm 4096      // B*T tokens
#define FF 4096      // ffn hidden

// ---------------- scratch (device globals; no allocation) ----------------
__device__ __half g_hh[Mm * Cc];        // LN output (fp16)
__device__ __half g_qh[Mm * Cc];
__device__ __half g_kh[Mm * Cc];
__device__ __half g_vh[Mm * Cc];
__device__ __half g_ah[Mm * Cc];        // attention output
__device__ __half g_ffh[Mm * FF];       // FFN hidden (fp16)
__device__ __half g_wch[8 * Cc * Cc];   // 8 CxC weights fp16
__device__ __half g_w1h[Cc * FF];
__device__ __half g_w2h[FF * Cc];
__device__ __half g_ench[Mm * Cc];      // encoder_out fp16

// ---------------- helpers ----------------
__device__ __forceinline__ void cp16(void* dst_smem, const void* src) {
    uint32_t sa = (uint32_t)__cvta_generic_to_shared(dst_smem);
    asm volatile("cp.async.cg.shared.global [%0], [%1], 16;\n" :: "r"(sa), "l"(src));
}
__device__ __forceinline__ void ldsm4(uint32_t r[4], uint32_t a) {
    asm volatile("ldmatrix.sync.aligned.m8n8.x4.shared.b16 {%0,%1,%2,%3}, [%4];"
                 : "=r"(r[0]), "=r"(r[1]), "=r"(r[2]), "=r"(r[3]) : "r"(a));
}
__device__ __forceinline__ void ldsm4t(uint32_t r[4], uint32_t a) {
    asm volatile("ldmatrix.sync.aligned.m8n8.x4.trans.shared.b16 {%0,%1,%2,%3}, [%4];"
                 : "=r"(r[0]), "=r"(r[1]), "=r"(r[2]), "=r"(r[3]) : "r"(a));
}
__device__ __forceinline__ void mma16(float c[4], const uint32_t a[4], const uint32_t b[2]) {
    asm volatile(
        "mma.sync.aligned.m16n8k16.row.col.f32.f16.f16.f32 "
        "{%0,%1,%2,%3}, {%4,%5,%6,%7}, {%8,%9}, {%0,%1,%2,%3};\n"
        : "+f"(c[0]), "+f"(c[1]), "+f"(c[2]), "+f"(c[3])
        : "r"(a[0]), "r"(a[1]), "r"(a[2]), "r"(a[3]), "r"(b[0]), "r"(b[1]));
}
__device__ __forceinline__ uint32_t h2pack(float lo, float hi) {
    __half2 h = __floats2half2_rn(lo, hi);
    return *reinterpret_cast<uint32_t*>(&h);
}

// ---------------- fused fp32 -> fp16 convert (all tensors, one launch) ----------------
#define S1_LOG 18
#define S2_LOG 20
#define N_S1 8
#define CVT_TOTAL ((N_S1 << S1_LOG) + (3 << S2_LOG))   // 5,242,880 float4

struct CvtArgs {
    const float* src[11];
    __half* dst[11];
};

__global__ __launch_bounds__(256)
void f2h_all(CvtArgs args) {
    const int nt = gridDim.x * blockDim.x;
    int i = blockIdx.x * blockDim.x + threadIdx.x;
#pragma unroll
    for (int rep = 0; rep < 4; rep++) {
        if (i < CVT_TOTAL) {
            int seg, off;
            if (i < (N_S1 << S1_LOG)) {
                seg = i >> S1_LOG;
                off = i & ((1 << S1_LOG) - 1);
            } else {
                const int j = i - (N_S1 << S1_LOG);
                seg = N_S1 + (j >> S2_LOG);
                off = j & ((1 << S2_LOG) - 1);
            }
            const float4 v = ((const float4*)args.src[seg])[off];
            ((uint2*)args.dst[seg])[off] = make_uint2(h2pack(v.x, v.y), h2pack(v.z, v.w));
        }
        i += nt;
    }
}

// ---------------- block reduction ----------------
__device__ __forceinline__ float block_sum_256(float v) {
    __shared__ float sh[8];
    const int lane = threadIdx.x & 31;
    const int w = threadIdx.x >> 5;
#pragma unroll
    for (int o = 16; o > 0; o >>= 1) v += __shfl_xor_sync(0xffffffffu, v, o);
    if (lane == 0) sh[w] = v;
    __syncthreads();
    float r = (lane < 8) ? sh[lane] : 0.f;
#pragma unroll
    for (int o = 4; o > 0; o >>= 1) r += __shfl_xor_sync(0xffffffffu, r, o);
    float total = __shfl_sync(0xffffffffu, r, 0);
    __syncthreads();
    return total;
}

// ---------------- layernorm (fp32 in, fp16 out) ----------------
__global__ __launch_bounds__(256)
void ln_kernel(const float* __restrict__ x, const float* __restrict__ g,
               const float* __restrict__ b, __half* __restrict__ out) {
    const size_t row = blockIdx.x;
    const int t = threadIdx.x;
    const float4 v = ((const float4*)(x + row * Cc))[t];
    float s = v.x + v.y + v.z + v.w;
    const float mean = block_sum_256(s) * (1.f / Cc);
    const float dx = v.x - mean, dy = v.y - mean, dz = v.z - mean, dw = v.w - mean;
    const float var = block_sum_256(dx*dx + dy*dy + dz*dz + dw*dw) * (1.f / Cc);
    const float inv = rsqrtf(var + 1e-5f);
    const float4 gg = ((const float4*)g)[t];
    const float4 bb = ((const float4*)b)[t];
    ((uint2*)(out + row * Cc))[t] = make_uint2(
        h2pack(dx * inv * gg.x + bb.x, dy * inv * gg.y + bb.y),
        h2pack(dz * inv * gg.z + bb.z, dw * inv * gg.w + bb.w));
}

// ---------------- fp16 tensor-core GEMM ----------------
// CTA 128x128, 8 warps (2m x 4n), warp 64x32, k-tile 64, 2-stage cp.async
// (next tile's loads issued BEFORE the wait — R9-validated structure).
#define GA_P 72                        // A smem pitch (halfs): 144B rows
#define GB_P 136                       // B smem pitch (halfs): 272B rows
#define GA_SZ (128 * GA_P)
#define GB_SZ (64 * GB_P)
#define GSTG (GA_SZ + GB_SZ)
#define GEMM_SMEM (2 * GSTG * 2)       // bytes (71680)

template<bool RELU, bool RES, bool OUTH>
__global__ __launch_bounds__(256, 2)
void gemm_h(const __half* __restrict__ A, const __half* __restrict__ W,
            const float* __restrict__ bias, const float* __restrict__ res,
            void* __restrict__ outp, int M, int N, int K) {
    extern __shared__ __half smh[];
    const uint32_t sbase = (uint32_t)__cvta_generic_to_shared(smh);

    const int m0 = blockIdx.y * 128;
    const int n0 = blockIdx.x * 128;
    const int t = threadIdx.x;
    const int lane = t & 31;
    const int wid = t >> 5;
    const int g = lane >> 2;
    const int tig = lane & 3;
    const int wm = (wid & 1) * 64;
    const int wn = (wid >> 1) * 32;

    float acc[4][4][4];
#pragma unroll
    for (int mi = 0; mi < 4; mi++)
#pragma unroll
        for (int ni = 0; ni < 4; ni++)
#pragma unroll
            for (int r = 0; r < 4; r++) acc[mi][ni][r] = 0.f;

    const int ntk = K >> 6;

    auto load_tile = [&](int kt, int s) {
        __half* As = smh + s * GSTG;
        __half* Bs = As + GA_SZ;
        const int k0 = kt * 64;
        // A: 128 rows x 8 segs (16B) = 1024 cp16 -> 4/thread
#pragma unroll
        for (int i = 0; i < 4; i++) {
            const int idx = t + i * 256;
            const int r = idx >> 3, sg = idx & 7;
            cp16(As + r * GA_P + sg * 8, A + (size_t)(m0 + r) * K + k0 + sg * 8);
        }
        // B: 64 rows x 16 segs = 1024 cp16 -> 4/thread
#pragma unroll
        for (int i = 0; i < 4; i++) {
            const int idx = t + i * 256;
            const int r = idx >> 4, sg = idx & 15;
            cp16(Bs + r * GB_P + sg * 8, W + (size_t)(k0 + r) * N + n0 + sg * 8);
        }
        asm volatile("cp.async.commit_group;\n");
    };

    load_tile(0, 0);

    for (int kt = 0; kt < ntk; kt++) {
        const int buf = kt & 1;
        if (kt + 1 < ntk) {
            load_tile(kt + 1, buf ^ 1);
            asm volatile("cp.async.wait_group 1;\n");
        } else {
            asm volatile("cp.async.wait_group 0;\n");
        }
        __syncthreads();

        const uint32_t ab = sbase + buf * GSTG * 2;          // A bytes
        const uint32_t bb = ab + GA_SZ * 2;                  // B bytes
#pragma unroll
        for (int ks = 0; ks < 4; ks++) {
            uint32_t af[4][4];
#pragma unroll
            for (int mi = 0; mi < 4; mi++)
                ldsm4(af[mi], ab + ((wm + mi * 16 + (lane & 15)) * GA_P
                                    + ks * 16 + (lane >> 4) * 8) * 2);
            uint32_t bf[2][4];
#pragma unroll
            for (int p = 0; p < 2; p++)
                ldsm4t(bf[p], bb + ((ks * 16 + (lane & 7) + ((lane >> 3) & 1) * 8) * GB_P
                                    + wn + p * 16 + (lane >> 4) * 8) * 2);
#pragma unroll
            for (int mi = 0; mi < 4; mi++)
#pragma unroll
                for (int ni = 0; ni < 4; ni++)
                    mma16(acc[mi][ni], af[mi], &bf[ni >> 1][(ni & 1) * 2]);
        }
        __syncthreads();
    }

    // epilogue
#pragma unroll
    for (int mi = 0; mi < 4; mi++) {
        const int m = m0 + wm + mi * 16 + g;
#pragma unroll
        for (int ni = 0; ni < 4; ni++) {
            const int n = n0 + wn + ni * 8 + tig * 2;
            float v0x = acc[mi][ni][0], v0y = acc[mi][ni][1];
            float v1x = acc[mi][ni][2], v1y = acc[mi][ni][3];
            if (bias) {
                const float b0 = bias[n], b1 = bias[n + 1];
                v0x += b0; v0y += b1; v1x += b0; v1y += b1;
            }
            if (RES) {
                const float2 r0 = *(const float2*)(res + (size_t)m * N + n);
                const float2 r1 = *(const float2*)(res + (size_t)(m + 8) * N + n);
                v0x += r0.x; v0y += r0.y; v1x += r1.x; v1y += r1.y;
            }
            if (RELU) {
                v0x = fmaxf(v0x, 0.f); v0y = fmaxf(v0y, 0.f);
                v1x = fmaxf(v1x, 0.f); v1y = fmaxf(v1y, 0.f);
            }
            if (OUTH) {
                __half* o = (__half*)outp;
                *(uint32_t*)(o + (size_t)m * N + n) = h2pack(v0x, v0y);
                *(uint32_t*)(o + (size_t)(m + 8) * N + n) = h2pack(v1x, v1y);
            } else {
                float* o = (float*)outp;
                *(float2*)(o + (size_t)m * N + n) = make_float2(v0x, v0y);
                *(float2*)(o + (size_t)(m + 8) * N + n) = make_float2(v1x, v1y);
            }
        }
    }
}

// ---------------- fp16 tensor-core flash attention ----------------
#define AP 72
#define AQ_SZ (64 * AP)                // halfs
#define ATTN_SMEM ((AQ_SZ * 5) * 2)    // Q + 2K + 2V, bytes (46080)

template<bool CAUSAL>
__global__ __launch_bounds__(128)
void attn_h(const __half* __restrict__ Qg, const __half* __restrict__ Kg,
            const __half* __restrict__ Vg, __half* __restrict__ Og) {
    extern __shared__ __half smh[];
    __half* Qs = smh;
    __half* Ks = smh + AQ_SZ;
    __half* Vs = Ks + 2 * AQ_SZ;
    const uint32_t sbase = (uint32_t)__cvta_generic_to_shared(smh);
    const uint32_t qb = sbase;
    const uint32_t kb = sbase + AQ_SZ * 2;
    const uint32_t vb = kb + 2 * AQ_SZ * 2;

    const int qt = blockIdx.x;
    const int bh = blockIdx.y;
    const int b = bh >> 4;
    const int h = bh & 15;
    const int q0 = qt * 64;
    const int t = threadIdx.x;
    const int lane = t & 31;
    const int w = t >> 5;
    const int g = lane >> 2;
    const int tig = lane & 3;
    const int wm = w * 16;

    const __half* Qbase = Qg + ((size_t)(b * Tt + q0)) * Cc + h * Dd;
    const __half* Kbase = Kg + ((size_t)(b * Tt)) * Cc + h * Dd;
    const __half* Vbase = Vg + ((size_t)(b * Tt)) * Cc + h * Dd;

#pragma unroll
    for (int i = 0; i < 4; i++) {
        const int idx = t + i * 128;
        const int r = idx >> 3, sg = idx & 7;
        cp16(Qs + r * AP + sg * 8, Qbase + (size_t)r * Cc + sg * 8);
        cp16(Ks + r * AP + sg * 8, Kbase + (size_t)r * Cc + sg * 8);
        cp16(Vs + r * AP + sg * 8, Vbase + (size_t)r * Cc + sg * 8);
    }
    asm volatile("cp.async.commit_group;\n");

    float m0r = -1e30f, m1r = -1e30f, l0 = 0.f, l1 = 0.f;
    float oacc[8][4];
#pragma unroll
    for (int nf = 0; nf < 8; nf++)
#pragma unroll
        for (int r = 0; r < 4; r++) oacc[nf][r] = 0.f;

    const int ktend = CAUSAL ? qt : (Tt / 64 - 1);
    for (int kt = 0; kt <= ktend; kt++) {
        const int buf = kt & 1;
        if (kt < ktend) {
            const __half* Kp = Kbase + (size_t)(kt + 1) * 64 * Cc;
            const __half* Vp = Vbase + (size_t)(kt + 1) * 64 * Cc;
            __half* Kd = Ks + (buf ^ 1) * AQ_SZ;
            __half* Vd = Vs + (buf ^ 1) * AQ_SZ;
#pragma unroll
            for (int i = 0; i < 4; i++) {
                const int idx = t + i * 128;
                const int r = idx >> 3, sg = idx & 7;
                cp16(Kd + r * AP + sg * 8, Kp + (size_t)r * Cc + sg * 8);
                cp16(Vd + r * AP + sg * 8, Vp + (size_t)r * Cc + sg * 8);
            }
            asm volatile("cp.async.commit_group;\n");
            asm volatile("cp.async.wait_group 1;\n");
        } else {
            asm volatile("cp.async.wait_group 0;\n");
        }
        __syncthreads();

        const uint32_t kbb = kb + buf * AQ_SZ * 2;
        const uint32_t vbb = vb + buf * AQ_SZ * 2;

        float sc[8][4];
#pragma unroll
        for (int nf = 0; nf < 8; nf++)
#pragma unroll
            for (int r = 0; r < 4; r++) sc[nf][r] = 0.f;
#pragma unroll
        for (int ks = 0; ks < 4; ks++) {
            uint32_t a[4];
            ldsm4(a, qb + ((wm + (lane & 15)) * AP + ks * 16 + (lane >> 4) * 8) * 2);
#pragma unroll
            for (int p = 0; p < 4; p++) {
                uint32_t bf[4];
                ldsm4(bf, kbb + ((p * 16 + (lane >> 4) * 8 + (lane & 7)) * AP
                                 + ks * 16 + ((lane >> 3) & 1) * 8) * 2);
                mma16(sc[2 * p], a, &bf[0]);
                mma16(sc[2 * p + 1], a, &bf[2]);
            }
        }

        const int r0g = q0 + wm + g;
        const int r1g = r0g + 8;
#pragma unroll
        for (int nf = 0; nf < 8; nf++) {
            sc[nf][0] *= 0.125f; sc[nf][1] *= 0.125f;
            sc[nf][2] *= 0.125f; sc[nf][3] *= 0.125f;
            if (CAUSAL && kt == qt) {
                const int c0 = kt * 64 + nf * 8 + tig * 2;
                if (c0 > r0g) sc[nf][0] = -1e30f;
                if (c0 + 1 > r0g) sc[nf][1] = -1e30f;
                if (c0 > r1g) sc[nf][2] = -1e30f;
                if (c0 + 1 > r1g) sc[nf][3] = -1e30f;
            }
        }

        float mx0 = -1e30f, mx1 = -1e30f;
#pragma unroll
        for (int nf = 0; nf < 8; nf++) {
            mx0 = fmaxf(mx0, fmaxf(sc[nf][0], sc[nf][1]));
            mx1 = fmaxf(mx1, fmaxf(sc[nf][2], sc[nf][3]));
        }
        mx0 = fmaxf(mx0, __shfl_xor_sync(0xffffffffu, mx0, 1));
        mx0 = fmaxf(mx0, __shfl_xor_sync(0xffffffffu, mx0, 2));
        mx1 = fmaxf(mx1, __shfl_xor_sync(0xffffffffu, mx1, 1));
        mx1 = fmaxf(mx1, __shfl_xor_sync(0xffffffffu, mx1, 2));
        const float nm0 = fmaxf(m0r, mx0);
        const float nm1 = fmaxf(m1r, mx1);
        const float al0 = __expf(m0r - nm0);
        const float al1 = __expf(m1r - nm1);
        float rs0 = 0.f, rs1 = 0.f;
#pragma unroll
        for (int nf = 0; nf < 8; nf++) {
            sc[nf][0] = __expf(sc[nf][0] - nm0);
            sc[nf][1] = __expf(sc[nf][1] - nm0);
            sc[nf][2] = __expf(sc[nf][2] - nm1);
            sc[nf][3] = __expf(sc[nf][3] - nm1);
            rs0 += sc[nf][0] + sc[nf][1];
            rs1 += sc[nf][2] + sc[nf][3];
        }
        rs0 += __shfl_xor_sync(0xffffffffu, rs0, 1);
        rs0 += __shfl_xor_sync(0xffffffffu, rs0, 2);
        rs1 += __shfl_xor_sync(0xffffffffu, rs1, 1);
        rs1 += __shfl_xor_sync(0xffffffffu, rs1, 2);
        l0 = l0 * al0 + rs0;
        l1 = l1 * al1 + rs1;
        m0r = nm0; m1r = nm1;
#pragma unroll
        for (int nf = 0; nf < 8; nf++) {
            oacc[nf][0] *= al0; oacc[nf][1] *= al0;
            oacc[nf][2] *= al1; oacc[nf][3] *= al1;
        }

#pragma unroll
        for (int ks = 0; ks < 4; ks++) {
            uint32_t a[4];
            a[0] = h2pack(sc[2 * ks][0], sc[2 * ks][1]);
            a[1] = h2pack(sc[2 * ks][2], sc[2 * ks][3]);
            a[2] = h2pack(sc[2 * ks + 1][0], sc[2 * ks + 1][1]);
            a[3] = h2pack(sc[2 * ks + 1][2], sc[2 * ks + 1][3]);
#pragma unroll
            for (int p = 0; p < 4; p++) {
                uint32_t bf[4];
                ldsm4t(bf, vbb + ((ks * 16 + (lane & 7) + ((lane >> 3) & 1) * 8) * AP
                                  + p * 16 + (lane >> 4) * 8) * 2);
                mma16(oacc[2 * p], a, &bf[0]);
                mma16(oacc[2 * p + 1], a, &bf[2]);
            }
        }
        __syncthreads();
    }

    const float inv0 = 1.f / l0;
    const float inv1 = 1.f / l1;
    __half* orow0 = Og + ((size_t)(b * Tt + q0 + wm + g)) * Cc + h * Dd;
    __half* orow1 = orow0 + (size_t)8 * Cc;
#pragma unroll
    for (int nf = 0; nf < 8; nf++) {
        *(uint32_t*)(orow0 + nf * 8 + tig * 2) = h2pack(oacc[nf][0] * inv0, oacc[nf][1] * inv0);
        *(uint32_t*)(orow1 + nf * 8 + tig * 2) = h2pack(oacc[nf][2] * inv1, oacc[nf][3] * inv1);
    }
}

// ---------------- driver ----------------
extern "C" void kernel_launch(void* const* d_in, const int* in_sizes, int n_in,
                              void* d_out, int out_size) {
    const float* x      = (const float*)d_in[0];
    const float* enc    = (const float*)d_in[1];
    const float* sa_wq  = (const float*)d_in[2];
    const float* sa_wk  = (const float*)d_in[3];
    const float* sa_wv  = (const float*)d_in[4];
    const float* sa_wo  = (const float*)d_in[5];
    const float* sa_bo  = (const float*)d_in[6];
    const float* ca_wq  = (const float*)d_in[7];
    const float* ca_wk  = (const float*)d_in[8];
    const float* ca_wv  = (const float*)d_in[9];
    const float* ca_wo  = (const float*)d_in[10];
    const float* ca_bo  = (const float*)d_in[11];
    const float* ff_w1  = (const float*)d_in[12];
    const float* ff_b1  = (const float*)d_in[13];
    const float* ff_w2  = (const float*)d_in[14];
    const float* ff_b2  = (const float*)d_in[15];
    const float* ln1_g  = (const float*)d_in[16];
    const float* ln1_b  = (const float*)d_in[17];
    const float* ln2_g  = (const float*)d_in[18];
    const float* ln2_b  = (const float*)d_in[19];
    const float* ln3_g  = (const float*)d_in[20];
    const float* ln3_b  = (const float*)d_in[21];
    float* out = (float*)d_out;

    __half *hh, *qh, *kh, *vh, *ah, *ffh, *wch, *w1h, *w2h, *ench;
    cudaGetSymbolAddress((void**)&hh,   g_hh);
    cudaGetSymbolAddress((void**)&qh,   g_qh);
    cudaGetSymbolAddress((void**)&kh,   g_kh);
    cudaGetSymbolAddress((void**)&vh,   g_vh);
    cudaGetSymbolAddress((void**)&ah,   g_ah);
    cudaGetSymbolAddress((void**)&ffh,  g_ffh);
    cudaGetSymbolAddress((void**)&wch,  g_wch);
    cudaGetSymbolAddress((void**)&w1h,  g_w1h);
    cudaGetSymbolAddress((void**)&w2h,  g_w2h);
    cudaGetSymbolAddress((void**)&ench, g_ench);

    cudaFuncSetAttribute((const void*)attn_h<true>,
                         cudaFuncAttributeMaxDynamicSharedMemorySize, ATTN_SMEM);
    cudaFuncSetAttribute((const void*)attn_h<false>,
                         cudaFuncAttributeMaxDynamicSharedMemorySize, ATTN_SMEM);
    cudaFuncSetAttribute((const void*)gemm_h<false, false, true>,
                         cudaFuncAttributeMaxDynamicSharedMemorySize, GEMM_SMEM);
    cudaFuncSetAttribute((const void*)gemm_h<false, true, false>,
                         cudaFuncAttributeMaxDynamicSharedMemorySize, GEMM_SMEM);
    cudaFuncSetAttribute((const void*)gemm_h<true, false, true>,
                         cudaFuncAttributeMaxDynamicSharedMemorySize, GEMM_SMEM);

    const int CC = Cc * Cc;

    // fused conversion: 8 CxC weights, ff_w1, ff_w2, enc — ONE launch
    __half* wp[8] = {wch + 0*CC, wch + 1*CC, wch + 2*CC, wch + 3*CC,
                     wch + 4*CC, wch + 5*CC, wch + 6*CC, wch + 7*CC};
    CvtArgs ca;
    const float* ws[8] = {sa_wq, sa_wk, sa_wv, sa_wo, ca_wq, ca_wk, ca_wv, ca_wo};
    for (int i = 0; i < 8; i++) { ca.src[i] = ws[i]; ca.dst[i] = wp[i]; }
    ca.src[8] = ff_w1; ca.dst[8] = w1h;
    ca.src[9] = ff_w2; ca.dst[9] = w2h;
    ca.src[10] = enc;  ca.dst[10] = ench;
    f2h_all<<<(CVT_TOTAL / 4 + 255) / 256, 256>>>(ca);

    const dim3 gP(Cc / 128, Mm / 128);     // 8 x 32
    const dim3 gF1(FF / 128, Mm / 128);    // 32 x 32
    const dim3 gA(Tt / 64, Bb * Hh);

    // ---- self-attention block ----
    ln_kernel<<<Mm, 256>>>(x, ln1_g, ln1_b, hh);
    gemm_h<false, false, true><<<gP, 256, GEMM_SMEM>>>(hh, wp[0], nullptr, nullptr, qh, Mm, Cc, Cc);
    gemm_h<false, false, true><<<gP, 256, GEMM_SMEM>>>(hh, wp[1], nullptr, nullptr, kh, Mm, Cc, Cc);
    gemm_h<false, false, true><<<gP, 256, GEMM_SMEM>>>(hh, wp[2], nullptr, nullptr, vh, Mm, Cc, Cc);
    attn_h<true><<<gA, 128, ATTN_SMEM>>>(qh, kh, vh, ah);
    gemm_h<false, true, false><<<gP, 256, GEMM_SMEM>>>(ah, wp[3], sa_bo, x, out, Mm, Cc, Cc);

    // ---- cross-attention block ----
    ln_kernel<<<Mm, 256>>>(out, ln2_g, ln2_b, hh);
    gemm_h<false, false, true><<<gP, 256, GEMM_SMEM>>>(hh,   wp[4], nullptr, nullptr, qh, Mm, Cc, Cc);
    gemm_h<false, false, true><<<gP, 256, GEMM_SMEM>>>(ench, wp[5], nullptr, nullptr, kh, Mm, Cc, Cc);
    gemm_h<false, false, true><<<gP, 256, GEMM_SMEM>>>(ench, wp[6], nullptr, nullptr, vh, Mm, Cc, Cc);
    attn_h<false><<<gA, 128, ATTN_SMEM>>>(qh, kh, vh, ah);
    gemm_h<false, true, false><<<gP, 256, GEMM_SMEM>>>(ah, wp[7], ca_bo, out, out, Mm, Cc, Cc);

    // ---- FFN block ----
    ln_kernel<<<Mm, 256>>>(out, ln3_g, ln3_b, hh);
    gemm_h<true,  false, true><<<gF1, 256, GEMM_SMEM>>>(hh,  w1h, ff_b1, nullptr, ffh, Mm, FF, Cc);
    gemm_h<false, true, false><<<gP,  256, GEMM_SMEM>>>(ffh, w2h, ff_b2, out, out, Mm, Cc, FF);
}

// round 14
// speedup vs baseline: 1.0498x; 1.0119x over previous
#include <cuda_runtime.h>
#include <cuda_fp16.h>
#include <cstdint>
#include <cstddef>

// Problem constants
#define Bb 4
#define Tt 1024
#define Cc 1024
#define Hh 16
#define Dd 64
#define Mm 4096      // B*T tokens
#define FF 4096      // ffn hidden

// ---------------- scratch (device globals; no allocation) ----------------
__device__ __half g_hh[Mm * Cc];          // LN output (fp16)
__device__ __half g_qkvh[Mm * 3 * Cc];    // fused self QKV activations
__device__ __half g_qh[Mm * Cc];          // cross Q
__device__ __half g_kvh[Mm * 2 * Cc];     // fused cross KV
__device__ __half g_ah[Mm * Cc];          // attention output
__device__ __half g_ffh[Mm * FF];         // FFN hidden
__device__ __half g_wqkv[Cc * 3 * Cc];    // fused self QKV weights
__device__ __half g_wkv[Cc * 2 * Cc];     // fused cross KV weights
__device__ __half g_wso[Cc * Cc];         // sa_wo
__device__ __half g_wcq[Cc * Cc];         // ca_wq
__device__ __half g_wco[Cc * Cc];         // ca_wo
__device__ __half g_w1h[Cc * FF];
__device__ __half g_w2h[FF * Cc];
__device__ __half g_ench[Mm * Cc];        // encoder_out fp16

// ---------------- helpers ----------------
__device__ __forceinline__ void cp16(void* dst_smem, const void* src) {
    uint32_t sa = (uint32_t)__cvta_generic_to_shared(dst_smem);
    asm volatile("cp.async.cg.shared.global [%0], [%1], 16;\n" :: "r"(sa), "l"(src));
}
__device__ __forceinline__ void ldsm4(uint32_t r[4], uint32_t a) {
    asm volatile("ldmatrix.sync.aligned.m8n8.x4.shared.b16 {%0,%1,%2,%3}, [%4];"
                 : "=r"(r[0]), "=r"(r[1]), "=r"(r[2]), "=r"(r[3]) : "r"(a));
}
__device__ __forceinline__ void ldsm4t(uint32_t r[4], uint32_t a) {
    asm volatile("ldmatrix.sync.aligned.m8n8.x4.trans.shared.b16 {%0,%1,%2,%3}, [%4];"
                 : "=r"(r[0]), "=r"(r[1]), "=r"(r[2]), "=r"(r[3]) : "r"(a));
}
__device__ __forceinline__ void mma16(float c[4], const uint32_t a[4], const uint32_t b[2]) {
    asm volatile(
        "mma.sync.aligned.m16n8k16.row.col.f32.f16.f16.f32 "
        "{%0,%1,%2,%3}, {%4,%5,%6,%7}, {%8,%9}, {%0,%1,%2,%3};\n"
        : "+f"(c[0]), "+f"(c[1]), "+f"(c[2]), "+f"(c[3])
        : "r"(a[0]), "r"(a[1]), "r"(a[2]), "r"(a[3]), "r"(b[0]), "r"(b[1]));
}
__device__ __forceinline__ uint32_t h2pack(float lo, float hi) {
    __half2 h = __floats2half2_rn(lo, hi);
    return *reinterpret_cast<uint32_t*>(&h);
}

// ---------------- fused fp32 -> fp16 convert with column-offset remap ----------------
// dst_uint2_idx = (off >> lrq)*pitch + (off & (2^lrq - 1)) + cbase   (units: uint2 = 4 halfs)
#define S1_LOG 18
#define S2_LOG 20
#define N_S1 8
#define CVT_TOTAL ((N_S1 << S1_LOG) + (3 << S2_LOG))   // 5,242,880 float4

struct CvtArgs {
    const float* src[11];
    uint2* dst[11];
    int pitch[11];
    int cbase[11];
    int lrq[11];
};

__global__ __launch_bounds__(256)
void f2h_all(CvtArgs args) {
    const int nt = gridDim.x * blockDim.x;
    int i = blockIdx.x * blockDim.x + threadIdx.x;
#pragma unroll
    for (int rep = 0; rep < 4; rep++) {
        if (i < CVT_TOTAL) {
            int seg, off;
            if (i < (N_S1 << S1_LOG)) {
                seg = i >> S1_LOG;
                off = i & ((1 << S1_LOG) - 1);
            } else {
                const int j = i - (N_S1 << S1_LOG);
                seg = N_S1 + (j >> S2_LOG);
                off = j & ((1 << S2_LOG) - 1);
            }
            const int lrq = args.lrq[seg];
            const int row = off >> lrq;
            const int c = off & ((1 << lrq) - 1);
            const float4 v = ((const float4*)args.src[seg])[off];
            args.dst[seg][row * args.pitch[seg] + c + args.cbase[seg]] =
                make_uint2(h2pack(v.x, v.y), h2pack(v.z, v.w));
        }
        i += nt;
    }
}

// ---------------- block reduction ----------------
__device__ __forceinline__ float block_sum_256(float v) {
    __shared__ float sh[8];
    const int lane = threadIdx.x & 31;
    const int w = threadIdx.x >> 5;
#pragma unroll
    for (int o = 16; o > 0; o >>= 1) v += __shfl_xor_sync(0xffffffffu, v, o);
    if (lane == 0) sh[w] = v;
    __syncthreads();
    float r = (lane < 8) ? sh[lane] : 0.f;
#pragma unroll
    for (int o = 4; o > 0; o >>= 1) r += __shfl_xor_sync(0xffffffffu, r, o);
    float total = __shfl_sync(0xffffffffu, r, 0);
    __syncthreads();
    return total;
}

// ---------------- layernorm (fp32 in, fp16 out) ----------------
__global__ __launch_bounds__(256)
void ln_kernel(const float* __restrict__ x, const float* __restrict__ g,
               const float* __restrict__ b, __half* __restrict__ out) {
    const size_t row = blockIdx.x;
    const int t = threadIdx.x;
    const float4 v = ((const float4*)(x + row * Cc))[t];
    float s = v.x + v.y + v.z + v.w;
    const float mean = block_sum_256(s) * (1.f / Cc);
    const float dx = v.x - mean, dy = v.y - mean, dz = v.z - mean, dw = v.w - mean;
    const float var = block_sum_256(dx*dx + dy*dy + dz*dz + dw*dw) * (1.f / Cc);
    const float inv = rsqrtf(var + 1e-5f);
    const float4 gg = ((const float4*)g)[t];
    const float4 bb = ((const float4*)b)[t];
    ((uint2*)(out + row * Cc))[t] = make_uint2(
        h2pack(dx * inv * gg.x + bb.x, dy * inv * gg.y + bb.y),
        h2pack(dz * inv * gg.z + bb.z, dw * inv * gg.w + bb.w));
}

// ---------------- fp16 tensor-core GEMM ----------------
// CTA 128x128, 4 warps (2m x 2n), warp tile 64x64, k-tile 64, 2-stage cp.async,
// next tile's loads issued BEFORE the wait (R9/R13-validated structure).
#define GA_P 72                        // A smem pitch (halfs): 144B rows
#define GB_P 136                       // B smem pitch (halfs): 272B rows
#define GA_SZ (128 * GA_P)
#define GB_SZ (64 * GB_P)
#define GSTG (GA_SZ + GB_SZ)
#define GEMM_SMEM (2 * GSTG * 2)       // bytes (71680)

template<bool RELU, bool RES, bool OUTH>
__global__ __launch_bounds__(128, 2)
void gemm_h(const __half* __restrict__ A, const __half* __restrict__ W,
            const float* __restrict__ bias, const float* __restrict__ res,
            void* __restrict__ outp, int M, int N, int K) {
    extern __shared__ __half smh[];
    const uint32_t sbase = (uint32_t)__cvta_generic_to_shared(smh);

    const int m0 = blockIdx.y * 128;
    const int n0 = blockIdx.x * 128;
    const int t = threadIdx.x;
    const int lane = t & 31;
    const int wid = t >> 5;
    const int g = lane >> 2;
    const int tig = lane & 3;
    const int wm = (wid & 1) * 64;
    const int wn = (wid >> 1) * 64;

    float acc[4][8][4];
#pragma unroll
    for (int mi = 0; mi < 4; mi++)
#pragma unroll
        for (int ni = 0; ni < 8; ni++)
#pragma unroll
            for (int r = 0; r < 4; r++) acc[mi][ni][r] = 0.f;

    const int ntk = K >> 6;

    auto load_tile = [&](int kt, int s) {
        __half* As = smh + s * GSTG;
        __half* Bs = As + GA_SZ;
        const int k0 = kt * 64;
        // A: 128 rows x 8 segs (16B) = 1024 cp16 -> 8/thread (128 thr)
#pragma unroll
        for (int i = 0; i < 8; i++) {
            const int idx = t + i * 128;
            const int r = idx >> 3, sg = idx & 7;
            cp16(As + r * GA_P + sg * 8, A + (size_t)(m0 + r) * K + k0 + sg * 8);
        }
        // B: 64 rows x 16 segs = 1024 cp16 -> 8/thread
#pragma unroll
        for (int i = 0; i < 8; i++) {
            const int idx = t + i * 128;
            const int r = idx >> 4, sg = idx & 15;
            cp16(Bs + r * GB_P + sg * 8, W + (size_t)(k0 + r) * N + n0 + sg * 8);
        }
        asm volatile("cp.async.commit_group;\n");
    };

    load_tile(0, 0);

    for (int kt = 0; kt < ntk; kt++) {
        const int buf = kt & 1;
        if (kt + 1 < ntk) {
            load_tile(kt + 1, buf ^ 1);
            asm volatile("cp.async.wait_group 1;\n");
        } else {
            asm volatile("cp.async.wait_group 0;\n");
        }
        __syncthreads();

        const uint32_t ab = sbase + buf * GSTG * 2;          // A bytes
        const uint32_t bb = ab + GA_SZ * 2;                  // B bytes
#pragma unroll
        for (int ks = 0; ks < 4; ks++) {
            uint32_t af[4][4];
#pragma unroll
            for (int mi = 0; mi < 4; mi++)
                ldsm4(af[mi], ab + ((wm + mi * 16 + (lane & 15)) * GA_P
                                    + ks * 16 + (lane >> 4) * 8) * 2);
            uint32_t bf[4][4];
#pragma unroll
            for (int p = 0; p < 4; p++)
                ldsm4t(bf[p], bb + ((ks * 16 + (lane & 7) + ((lane >> 3) & 1) * 8) * GB_P
                                    + wn + p * 16 + (lane >> 4) * 8) * 2);
#pragma unroll
            for (int mi = 0; mi < 4; mi++)
#pragma unroll
                for (int ni = 0; ni < 8; ni++)
                    mma16(acc[mi][ni], af[mi], &bf[ni >> 1][(ni & 1) * 2]);
        }
        __syncthreads();
    }

    // epilogue
#pragma unroll
    for (int mi = 0; mi < 4; mi++) {
        const int m = m0 + wm + mi * 16 + g;
#pragma unroll
        for (int ni = 0; ni < 8; ni++) {
            const int n = n0 + wn + ni * 8 + tig * 2;
            float v0x = acc[mi][ni][0], v0y = acc[mi][ni][1];
            float v1x = acc[mi][ni][2], v1y = acc[mi][ni][3];
            if (bias) {
                const float b0 = bias[n], b1 = bias[n + 1];
                v0x += b0; v0y += b1; v1x += b0; v1y += b1;
            }
            if (RES) {
                const float2 r0 = *(const float2*)(res + (size_t)m * N + n);
                const float2 r1 = *(const float2*)(res + (size_t)(m + 8) * N + n);
                v0x += r0.x; v0y += r0.y; v1x += r1.x; v1y += r1.y;
            }
            if (RELU) {
                v0x = fmaxf(v0x, 0.f); v0y = fmaxf(v0y, 0.f);
                v1x = fmaxf(v1x, 0.f); v1y = fmaxf(v1y, 0.f);
            }
            if (OUTH) {
                __half* o = (__half*)outp;
                *(uint32_t*)(o + (size_t)m * N + n) = h2pack(v0x, v0y);
                *(uint32_t*)(o + (size_t)(m + 8) * N + n) = h2pack(v1x, v1y);
            } else {
                float* o = (float*)outp;
                *(float2*)(o + (size_t)m * N + n) = make_float2(v0x, v0y);
                *(float2*)(o + (size_t)(m + 8) * N + n) = make_float2(v1x, v1y);
            }
        }
    }
}

// ---------------- fp16 tensor-core flash attention (strided Q/KV) ----------------
#define AP 72
#define AQ_SZ (64 * AP)                // halfs
#define ATTN_SMEM ((AQ_SZ * 5) * 2)    // Q + 2K + 2V, bytes (46080)

template<bool CAUSAL>
__global__ __launch_bounds__(128)
void attn_h(const __half* __restrict__ Qg, const __half* __restrict__ Kg,
            const __half* __restrict__ Vg, __half* __restrict__ Og,
            int sq, int skv) {
    extern __shared__ __half smh[];
    __half* Qs = smh;
    __half* Ks = smh + AQ_SZ;
    __half* Vs = Ks + 2 * AQ_SZ;
    const uint32_t sbase = (uint32_t)__cvta_generic_to_shared(smh);
    const uint32_t qb = sbase;
    const uint32_t kb = sbase + AQ_SZ * 2;
    const uint32_t vb = kb + 2 * AQ_SZ * 2;

    const int qt = blockIdx.x;
    const int bh = blockIdx.y;
    const int b = bh >> 4;
    const int h = bh & 15;
    const int q0 = qt * 64;
    const int t = threadIdx.x;
    const int lane = t & 31;
    const int w = t >> 5;
    const int g = lane >> 2;
    const int tig = lane & 3;
    const int wm = w * 16;

    const __half* Qbase = Qg + ((size_t)(b * Tt + q0)) * sq + h * Dd;
    const __half* Kbase = Kg + ((size_t)(b * Tt)) * skv + h * Dd;
    const __half* Vbase = Vg + ((size_t)(b * Tt)) * skv + h * Dd;

#pragma unroll
    for (int i = 0; i < 4; i++) {
        const int idx = t + i * 128;
        const int r = idx >> 3, sg = idx & 7;
        cp16(Qs + r * AP + sg * 8, Qbase + (size_t)r * sq + sg * 8);
        cp16(Ks + r * AP + sg * 8, Kbase + (size_t)r * skv + sg * 8);
        cp16(Vs + r * AP + sg * 8, Vbase + (size_t)r * skv + sg * 8);
    }
    asm volatile("cp.async.commit_group;\n");

    float m0r = -1e30f, m1r = -1e30f, l0 = 0.f, l1 = 0.f;
    float oacc[8][4];
#pragma unroll
    for (int nf = 0; nf < 8; nf++)
#pragma unroll
        for (int r = 0; r < 4; r++) oacc[nf][r] = 0.f;

    const int ktend = CAUSAL ? qt : (Tt / 64 - 1);
    for (int kt = 0; kt <= ktend; kt++) {
        const int buf = kt & 1;
        if (kt < ktend) {
            const __half* Kp = Kbase + (size_t)(kt + 1) * 64 * skv;
            const __half* Vp = Vbase + (size_t)(kt + 1) * 64 * skv;
            __half* Kd = Ks + (buf ^ 1) * AQ_SZ;
            __half* Vd = Vs + (buf ^ 1) * AQ_SZ;
#pragma unroll
            for (int i = 0; i < 4; i++) {
                const int idx = t + i * 128;
                const int r = idx >> 3, sg = idx & 7;
                cp16(Kd + r * AP + sg * 8, Kp + (size_t)r * skv + sg * 8);
                cp16(Vd + r * AP + sg * 8, Vp + (size_t)r * skv + sg * 8);
            }
            asm volatile("cp.async.commit_group;\n");
            asm volatile("cp.async.wait_group 1;\n");
        } else {
            asm volatile("cp.async.wait_group 0;\n");
        }
        __syncthreads();

        const uint32_t kbb = kb + buf * AQ_SZ * 2;
        const uint32_t vbb = vb + buf * AQ_SZ * 2;

        float sc[8][4];
#pragma unroll
        for (int nf = 0; nf < 8; nf++)
#pragma unroll
            for (int r = 0; r < 4; r++) sc[nf][r] = 0.f;
#pragma unroll
        for (int ks = 0; ks < 4; ks++) {
            uint32_t a[4];
            ldsm4(a, qb + ((wm + (lane & 15)) * AP + ks * 16 + (lane >> 4) * 8) * 2);
#pragma unroll
            for (int p = 0; p < 4; p++) {
                uint32_t bf[4];
                ldsm4(bf, kbb + ((p * 16 + (lane >> 4) * 8 + (lane & 7)) * AP
                                 + ks * 16 + ((lane >> 3) & 1) * 8) * 2);
                mma16(sc[2 * p], a, &bf[0]);
                mma16(sc[2 * p + 1], a, &bf[2]);
            }
        }

        const int r0g = q0 + wm + g;
        const int r1g = r0g + 8;
#pragma unroll
        for (int nf = 0; nf < 8; nf++) {
            sc[nf][0] *= 0.125f; sc[nf][1] *= 0.125f;
            sc[nf][2] *= 0.125f; sc[nf][3] *= 0.125f;
            if (CAUSAL && kt == qt) {
                const int c0 = kt * 64 + nf * 8 + tig * 2;
                if (c0 > r0g) sc[nf][0] = -1e30f;
                if (c0 + 1 > r0g) sc[nf][1] = -1e30f;
                if (c0 > r1g) sc[nf][2] = -1e30f;
                if (c0 + 1 > r1g) sc[nf][3] = -1e30f;
            }
        }

        float mx0 = -1e30f, mx1 = -1e30f;
#pragma unroll
        for (int nf = 0; nf < 8; nf++) {
            mx0 = fmaxf(mx0, fmaxf(sc[nf][0], sc[nf][1]));
            mx1 = fmaxf(mx1, fmaxf(sc[nf][2], sc[nf][3]));
        }
        mx0 = fmaxf(mx0, __shfl_xor_sync(0xffffffffu, mx0, 1));
        mx0 = fmaxf(mx0, __shfl_xor_sync(0xffffffffu, mx0, 2));
        mx1 = fmaxf(mx1, __shfl_xor_sync(0xffffffffu, mx1, 1));
        mx1 = fmaxf(mx1, __shfl_xor_sync(0xffffffffu, mx1, 2));
        const float nm0 = fmaxf(m0r, mx0);
        const float nm1 = fmaxf(m1r, mx1);
        const float al0 = __expf(m0r - nm0);
        const float al1 = __expf(m1r - nm1);
        float rs0 = 0.f, rs1 = 0.f;
#pragma unroll
        for (int nf = 0; nf < 8; nf++) {
            sc[nf][0] = __expf(sc[nf][0] - nm0);
            sc[nf][1] = __expf(sc[nf][1] - nm0);
            sc[nf][2] = __expf(sc[nf][2] - nm1);
            sc[nf][3] = __expf(sc[nf][3] - nm1);
            rs0 += sc[nf][0] + sc[nf][1];
            rs1 += sc[nf][2] + sc[nf][3];
        }
        rs0 += __shfl_xor_sync(0xffffffffu, rs0, 1);
        rs0 += __shfl_xor_sync(0xffffffffu, rs0, 2);
        rs1 += __shfl_xor_sync(0xffffffffu, rs1, 1);
        rs1 += __shfl_xor_sync(0xffffffffu, rs1, 2);
        l0 = l0 * al0 + rs0;
        l1 = l1 * al1 + rs1;
        m0r = nm0; m1r = nm1;
#pragma unroll
        for (int nf = 0; nf < 8; nf++) {
            oacc[nf][0] *= al0; oacc[nf][1] *= al0;
            oacc[nf][2] *= al1; oacc[nf][3] *= al1;
        }

#pragma unroll
        for (int ks = 0; ks < 4; ks++) {
            uint32_t a[4];
            a[0] = h2pack(sc[2 * ks][0], sc[2 * ks][1]);
            a[1] = h2pack(sc[2 * ks][2], sc[2 * ks][3]);
            a[2] = h2pack(sc[2 * ks + 1][0], sc[2 * ks + 1][1]);
            a[3] = h2pack(sc[2 * ks + 1][2], sc[2 * ks + 1][3]);
#pragma unroll
            for (int p = 0; p < 4; p++) {
                uint32_t bf[4];
                ldsm4t(bf, vbb + ((ks * 16 + (lane & 7) + ((lane >> 3) & 1) * 8) * AP
                                  + p * 16 + (lane >> 4) * 8) * 2);
                mma16(oacc[2 * p], a, &bf[0]);
                mma16(oacc[2 * p + 1], a, &bf[2]);
            }
        }
        __syncthreads();
    }

    const float inv0 = 1.f / l0;
    const float inv1 = 1.f / l1;
    __half* orow0 = Og + ((size_t)(b * Tt + q0 + wm + g)) * Cc + h * Dd;
    __half* orow1 = orow0 + (size_t)8 * Cc;
#pragma unroll
    for (int nf = 0; nf < 8; nf++) {
        *(uint32_t*)(orow0 + nf * 8 + tig * 2) = h2pack(oacc[nf][0] * inv0, oacc[nf][1] * inv0);
        *(uint32_t*)(orow1 + nf * 8 + tig * 2) = h2pack(oacc[nf][2] * inv1, oacc[nf][3] * inv1);
    }
}

// ---------------- driver ----------------
extern "C" void kernel_launch(void* const* d_in, const int* in_sizes, int n_in,
                              void* d_out, int out_size) {
    const float* x      = (const float*)d_in[0];
    const float* enc    = (const float*)d_in[1];
    const float* sa_wq  = (const float*)d_in[2];
    const float* sa_wk  = (const float*)d_in[3];
    const float* sa_wv  = (const float*)d_in[4];
    const float* sa_wo  = (const float*)d_in[5];
    const float* sa_bo  = (const float*)d_in[6];
    const float* ca_wq  = (const float*)d_in[7];
    const float* ca_wk  = (const float*)d_in[8];
    const float* ca_wv  = (const float*)d_in[9];
    const float* ca_wo  = (const float*)d_in[10];
    const float* ca_bo  = (const float*)d_in[11];
    const float* ff_w1  = (const float*)d_in[12];
    const float* ff_b1  = (const float*)d_in[13];
    const float* ff_w2  = (const float*)d_in[14];
    const float* ff_b2  = (const float*)d_in[15];
    const float* ln1_g  = (const float*)d_in[16];
    const float* ln1_b  = (const float*)d_in[17];
    const float* ln2_g  = (const float*)d_in[18];
    const float* ln2_b  = (const float*)d_in[19];
    const float* ln3_g  = (const float*)d_in[20];
    const float* ln3_b  = (const float*)d_in[21];
    float* out = (float*)d_out;

    __half *hh, *qkvh, *qh, *kvh, *ah, *ffh, *wqkv, *wkv, *wso, *wcq, *wco, *w1h, *w2h, *ench;
    cudaGetSymbolAddress((void**)&hh,   g_hh);
    cudaGetSymbolAddress((void**)&qkvh, g_qkvh);
    cudaGetSymbolAddress((void**)&qh,   g_qh);
    cudaGetSymbolAddress((void**)&kvh,  g_kvh);
    cudaGetSymbolAddress((void**)&ah,   g_ah);
    cudaGetSymbolAddress((void**)&ffh,  g_ffh);
    cudaGetSymbolAddress((void**)&wqkv, g_wqkv);
    cudaGetSymbolAddress((void**)&wkv,  g_wkv);
    cudaGetSymbolAddress((void**)&wso,  g_wso);
    cudaGetSymbolAddress((void**)&wcq,  g_wcq);
    cudaGetSymbolAddress((void**)&wco,  g_wco);
    cudaGetSymbolAddress((void**)&w1h,  g_w1h);
    cudaGetSymbolAddress((void**)&w2h,  g_w2h);
    cudaGetSymbolAddress((void**)&ench, g_ench);

    cudaFuncSetAttribute((const void*)attn_h<true>,
                         cudaFuncAttributeMaxDynamicSharedMemorySize, ATTN_SMEM);
    cudaFuncSetAttribute((const void*)attn_h<false>,
                         cudaFuncAttributeMaxDynamicSharedMemorySize, ATTN_SMEM);
    cudaFuncSetAttribute((const void*)gemm_h<false, false, true>,
                         cudaFuncAttributeMaxDynamicSharedMemorySize, GEMM_SMEM);
    cudaFuncSetAttribute((const void*)gemm_h<false, true, false>,
                         cudaFuncAttributeMaxDynamicSharedMemorySize, GEMM_SMEM);
    cudaFuncSetAttribute((const void*)gemm_h<true, false, true>,
                         cudaFuncAttributeMaxDynamicSharedMemorySize, GEMM_SMEM);

    // fused conversion — ONE launch.
    // seg 0-2: sa_wq/wk/wv -> wqkv [1024][3072]; seg 3: sa_wo; seg 4: ca_wq;
    // seg 5-6: ca_wk/wv -> wkv [1024][2048]; seg 7: ca_wo; seg 8: ff_w1; seg 9: ff_w2; seg 10: enc.
    CvtArgs ca;
    const float* srcs[11] = {sa_wq, sa_wk, sa_wv, sa_wo, ca_wq, ca_wk, ca_wv, ca_wo,
                             ff_w1, ff_w2, enc};
    __half* dsth[11] = {wqkv, wqkv, wqkv, wso, wcq, wkv, wkv, wco, w1h, w2h, ench};
    const int pitches[11] = {768, 768, 768, 256, 256, 512, 512, 256, 1024, 256, 256};
    const int cbases[11]  = {0, 256, 512, 0, 0, 0, 256, 0, 0, 0, 0};
    const int lrqs[11]    = {8, 8, 8, 8, 8, 8, 8, 8, 10, 8, 8};
    for (int i = 0; i < 11; i++) {
        ca.src[i] = srcs[i];
        ca.dst[i] = (uint2*)dsth[i];
        ca.pitch[i] = pitches[i];
        ca.cbase[i] = cbases[i];
        ca.lrq[i] = lrqs[i];
    }
    f2h_all<<<(CVT_TOTAL / 4 + 255) / 256, 256>>>(ca);

    const dim3 gP(Cc / 128, Mm / 128);          // 8 x 32
    const dim3 gQKV(3 * Cc / 128, Mm / 128);    // 24 x 32
    const dim3 gKV(2 * Cc / 128, Mm / 128);     // 16 x 32
    const dim3 gF1(FF / 128, Mm / 128);         // 32 x 32
    const dim3 gA(Tt / 64, Bb * Hh);

    // ---- self-attention block ----
    ln_kernel<<<Mm, 256>>>(x, ln1_g, ln1_b, hh);
    gemm_h<false, false, true><<<gQKV, 128, GEMM_SMEM>>>(hh, wqkv, nullptr, nullptr, qkvh, Mm, 3 * Cc, Cc);
    attn_h<true><<<gA, 128, ATTN_SMEM>>>(qkvh, qkvh + Cc, qkvh + 2 * Cc, ah, 3 * Cc, 3 * Cc);
    gemm_h<false, true, false><<<gP, 128, GEMM_SMEM>>>(ah, wso, sa_bo, x, out, Mm, Cc, Cc);

    // ---- cross-attention block ----
    ln_kernel<<<Mm, 256>>>(out, ln2_g, ln2_b, hh);
    gemm_h<false, false, true><<<gP, 128, GEMM_SMEM>>>(hh, wcq, nullptr, nullptr, qh, Mm, Cc, Cc);
    gemm_h<false, false, true><<<gKV, 128, GEMM_SMEM>>>(ench, wkv, nullptr, nullptr, kvh, Mm, 2 * Cc, Cc);
    attn_h<false><<<gA, 128, ATTN_SMEM>>>(qh, kvh, kvh + Cc, ah, Cc, 2 * Cc);
    gemm_h<false, true, false><<<gP, 128, GEMM_SMEM>>>(ah, wco, ca_bo, out, out, Mm, Cc, Cc);

    // ---- FFN block ----
    ln_kernel<<<Mm, 256>>>(out, ln3_g, ln3_b, hh);
    gemm_h<true,  false, true><<<gF1, 128, GEMM_SMEM>>>(hh,  w1h, ff_b1, nullptr, ffh, Mm, FF, Cc);
    gemm_h<false, true, false><<<gP,  128, GEMM_SMEM>>>(ffh, w2h, ff_b2, out, out, Mm, Cc, FF);
}